// round 2
// baseline (speedup 1.0000x reference)
#include <cuda_runtime.h>
#include <math.h>

#define N_PTS 20000
#define M_PTS 160000
#define CI 128
#define CO 64
#define GD 34
#define GSZ (GD*GD*GD)

// ---------------- device scratch (no allocs allowed) ----------------
__device__ int   g_pgrid[GSZ];            // parent index grid, padded [-1..32] per axis
__device__ float g_h[N_PTS*CI];           // silu(gn1(x)) per parent
__device__ float g_skip[N_PTS*CO];        // x_feats @ Ws + bs per parent
__device__ float g_mid[M_PTS*CO];         // conv1 output per child
__device__ float g_act[M_PTS*CO];         // silu(gn2(mid))
__device__ float g_weff[8*8*CI*CO];       // folded conv1 weights [o][n][cin][cout]
__device__ float g_sum1[CI], g_sq1[CI], g_mu1[32], g_rs1[32];
__device__ float g_sum2[CO], g_sq2[CO], g_mu2[32], g_rs2[32];

// ---------------- packed f32x2 helpers ----------------
__device__ __forceinline__ unsigned long long dup2(float a){
    unsigned long long r;
    asm("mov.b64 %0, {%1, %1};" : "=l"(r) : "f"(a));
    return r;
}
__device__ __forceinline__ void ffma2(unsigned long long &acc, unsigned long long a, unsigned long long b){
    asm("fma.rn.f32x2 %0, %1, %2, %0;" : "+l"(acc) : "l"(a), "l"(b));
}
__device__ __forceinline__ void unpack2(unsigned long long v, float &lo, float &hi){
    asm("mov.b64 {%0, %1}, %2;" : "=f"(lo), "=f"(hi) : "l"(v));
}

// ---------------- small kernels ----------------
__global__ void k_init(){
    int i = blockIdx.x*256 + threadIdx.x;
    if (i < GSZ) g_pgrid[i] = -1;
    if (i < CI){ g_sum1[i]=0.f; g_sq1[i]=0.f; }
    if (i < CO){ g_sum2[i]=0.f; g_sq2[i]=0.f; }
}

__global__ void k_scatter(const int* __restrict__ coords){
    int p = blockIdx.x*256 + threadIdx.x;
    if (p < N_PTS){
        int x=coords[p*4+1], y=coords[p*4+2], z=coords[p*4+3];
        g_pgrid[((x+1)*GD + (y+1))*GD + (z+1)] = p;
    }
}

__global__ void k_stats1(const float* __restrict__ xf){
    int c = threadIdx.x;            // 128 threads = channels
    float s=0.f, s2=0.f;
    for (int r = blockIdx.x; r < N_PTS; r += gridDim.x){
        float v = xf[r*CI + c]; s += v; s2 += v*v;
    }
    atomicAdd(&g_sum1[c], s); atomicAdd(&g_sq1[c], s2);
}

__global__ void k_fin1(){
    int g = threadIdx.x;
    if (g < 32){
        float s=0.f, s2=0.f;
        for (int j=0;j<4;j++){ s += g_sum1[g*4+j]; s2 += g_sq1[g*4+j]; }
        float inv = 1.f/(float)(N_PTS*4);
        float mu = s*inv;
        float var = s2*inv - mu*mu;
        g_mu1[g] = mu; g_rs1[g] = rsqrtf(var + 1e-5f);
    }
}

__global__ void k_h(const float* __restrict__ xf,
                    const float* __restrict__ gma, const float* __restrict__ bta){
    int i = blockIdx.x*256 + threadIdx.x;     // exact: N_PTS*CI multiple of 256
    int c = i & (CI-1); int g = c >> 2;
    float v = (xf[i] - g_mu1[g])*g_rs1[g]*gma[c] + bta[c];
    g_h[i] = v / (1.f + expf(-v));
}

// Fold 27 child-level taps into 8 parent-level neighbor matrices per child parity o.
__global__ void k_weff(const float* __restrict__ W1){
    int idx = blockIdx.x*256 + threadIdx.x;   // 8*8*128*64 = 524288 exact
    int cout = idx & 63, cin = (idx>>6)&127, n = (idx>>13)&7, o = idx>>16;
    int d0=(o>>2)&1, d1=(o>>1)&1, d2=o&1;
    int n0=(n>>2)&1, n1=(n>>1)&1, n2=n&1;
    float s = 0.f;
    for (int i=0;i<3;i++){
        int t0=d0+i-1; int p0=(t0>=2)?1:((t0>=0)?0:-1);
        if (p0 - d0 + 1 != n0) continue;
        for (int j=0;j<3;j++){
            int t1=d1+j-1; int p1=(t1>=2)?1:((t1>=0)?0:-1);
            if (p1 - d1 + 1 != n1) continue;
            for (int k=0;k<3;k++){
                int t2=d2+k-1; int p2=(t2>=2)?1:((t2>=0)?0:-1);
                if (p2 - d2 + 1 != n2) continue;
                s += W1[(((i*3+j)*3+k)*CI + cin)*CO + cout];
            }
        }
    }
    g_weff[idx] = s;
}

// ---------------- skip GEMM: 20000x128 @ 128x64 (tiny; plain fp32) ----------------
__device__ __forceinline__ void mma_row(float4 a, float4 w0, float4 w1, float4 w2, float4 w3,
                                        float acc[4]){
    acc[0]=fmaf(a.x,w0.x,acc[0]); acc[0]=fmaf(a.y,w1.x,acc[0]); acc[0]=fmaf(a.z,w2.x,acc[0]); acc[0]=fmaf(a.w,w3.x,acc[0]);
    acc[1]=fmaf(a.x,w0.y,acc[1]); acc[1]=fmaf(a.y,w1.y,acc[1]); acc[1]=fmaf(a.z,w2.y,acc[1]); acc[1]=fmaf(a.w,w3.y,acc[1]);
    acc[2]=fmaf(a.x,w0.z,acc[2]); acc[2]=fmaf(a.y,w1.z,acc[2]); acc[2]=fmaf(a.z,w2.z,acc[2]); acc[2]=fmaf(a.w,w3.z,acc[2]);
    acc[3]=fmaf(a.x,w0.w,acc[3]); acc[3]=fmaf(a.y,w1.w,acc[3]); acc[3]=fmaf(a.z,w2.w,acc[3]); acc[3]=fmaf(a.w,w3.w,acc[3]);
}

__global__ __launch_bounds__(256) void k_skip(const float* __restrict__ xf,
                                              const float* __restrict__ Ws,
                                              const float* __restrict__ bs){
    __shared__ __align__(16) float A_s[64][68];
    __shared__ __align__(16) float W_s[64][68];
    int t = threadIdx.x;
    int p0 = blockIdx.x*64;
    float acc[4][4] = {};
    int tr = t>>4, tc = t&15;
    for (int ck = 0; ck < 2; ck++){
        __syncthreads();
        #pragma unroll
        for (int rep = 0; rep < 4; rep++){
            int idx = rep*256 + t;
            int r = idx>>4, kv = idx&15;
            int p = p0 + r;
            float4 v = make_float4(0.f,0.f,0.f,0.f);
            if (p < N_PTS) v = *(const float4*)&xf[p*CI + ck*64 + kv*4];
            *(float4*)&A_s[r][kv*4] = v;
            *(float4*)&W_s[r][kv*4] = *(const float4*)&Ws[(ck*64 + r)*CO + kv*4];
        }
        __syncthreads();
        #pragma unroll
        for (int kk = 0; kk < 64; kk += 4){
            float4 w0 = *(float4*)&W_s[kk+0][tc*4];
            float4 w1 = *(float4*)&W_s[kk+1][tc*4];
            float4 w2 = *(float4*)&W_s[kk+2][tc*4];
            float4 w3 = *(float4*)&W_s[kk+3][tc*4];
            #pragma unroll
            for (int i = 0; i < 4; i++){
                float4 a = *(float4*)&A_s[tr*4+i][kk];
                mma_row(a, w0, w1, w2, w3, acc[i]);
            }
        }
    }
    #pragma unroll
    for (int i = 0; i < 4; i++){
        int p = p0 + tr*4 + i;
        if (p < N_PTS){
            float4 r;
            r.x = acc[i][0] + bs[tc*4+0];
            r.y = acc[i][1] + bs[tc*4+1];
            r.z = acc[i][2] + bs[tc*4+2];
            r.w = acc[i][3] + bs[tc*4+3];
            *(float4*)&g_skip[p*CO + tc*4] = r;
        }
    }
}

// ---------------- packed-f32x2 inner product step ----------------
// acc[2 rows][4 ull] over couts tc*8..tc*8+7, k block of 4
__device__ __forceinline__ void conv_tile_step(const float A_s[64][68], const float W_s[64][68],
                                               int kk, int tr, int tc,
                                               unsigned long long acc[2][4]){
    unsigned long long w[4][4];
    #pragma unroll
    for (int j = 0; j < 4; j++){
        ulonglong2 wa = *(const ulonglong2*)&W_s[kk+j][tc*8];
        ulonglong2 wb = *(const ulonglong2*)&W_s[kk+j][tc*8+4];
        w[j][0]=wa.x; w[j][1]=wa.y; w[j][2]=wb.x; w[j][3]=wb.y;
    }
    #pragma unroll
    for (int i = 0; i < 2; i++){
        float4 a = *(const float4*)&A_s[tr*2+i][kk];
        unsigned long long d0=dup2(a.x), d1=dup2(a.y), d2=dup2(a.z), d3=dup2(a.w);
        #pragma unroll
        for (int q = 0; q < 4; q++){
            ffma2(acc[i][q], d0, w[0][q]);
            ffma2(acc[i][q], d1, w[1][q]);
            ffma2(acc[i][q], d2, w[2][q]);
            ffma2(acc[i][q], d3, w[3][q]);
        }
    }
}

// ---------------- conv1: per child parity o, 8 parent neighbors, folded weights ----------------
__global__ __launch_bounds__(256) void k_conv1(const int* __restrict__ coords,
                                               const float* __restrict__ b1){
    __shared__ __align__(16) float A_s[64][68];
    __shared__ __align__(16) float W_s[64][68];
    __shared__ int   q_s[64][8];
    int t = threadIdx.x;
    int p0 = blockIdx.x*64;
    int o  = blockIdx.y;
    int dx=(o>>2)&1, dy=(o>>1)&1, dz=o&1;
    for (int e = t; e < 512; e += 256){
        int r = e>>3, n = e&7;
        int p = p0 + r; int q = -1;
        if (p < N_PTS){
            int x=coords[p*4+1], y=coords[p*4+2], z=coords[p*4+3];
            int ox = dx-1+((n>>2)&1), oy = dy-1+((n>>1)&1), oz = dz-1+(n&1);
            q = g_pgrid[((x+ox+1)*GD + (y+oy+1))*GD + (z+oz+1)];
        }
        q_s[r][n] = q;
    }
    unsigned long long acc[2][4] = {};
    int tr = t>>3, tc = t&7;
    for (int n = 0; n < 8; n++){
        const float* Wn = g_weff + (o*8 + n)*CI*CO;
        for (int ck = 0; ck < 2; ck++){
            __syncthreads();
            #pragma unroll
            for (int rep = 0; rep < 4; rep++){
                int idx = rep*256 + t;
                int r = idx>>4, kv = idx&15;
                int q = q_s[r][n];
                float4 v = make_float4(0.f,0.f,0.f,0.f);
                if (q >= 0) v = *(const float4*)&g_h[q*CI + ck*64 + kv*4];
                *(float4*)&A_s[r][kv*4] = v;
                *(float4*)&W_s[r][kv*4] = *(const float4*)&Wn[(ck*64 + r)*CO + kv*4];
            }
            __syncthreads();
            #pragma unroll
            for (int kk = 0; kk < 64; kk += 4)
                conv_tile_step(A_s, W_s, kk, tr, tc, acc);
        }
    }
    #pragma unroll
    for (int i = 0; i < 2; i++){
        int p = p0 + tr*2 + i;
        if (p < N_PTS){
            float o8[8];
            #pragma unroll
            for (int q = 0; q < 4; q++) unpack2(acc[i][q], o8[2*q], o8[2*q+1]);
            float* dst = &g_mid[(p*8 + o)*CO + tc*8];
            float4 r0, r1;
            r0.x=o8[0]+b1[tc*8+0]; r0.y=o8[1]+b1[tc*8+1]; r0.z=o8[2]+b1[tc*8+2]; r0.w=o8[3]+b1[tc*8+3];
            r1.x=o8[4]+b1[tc*8+4]; r1.y=o8[5]+b1[tc*8+5]; r1.z=o8[6]+b1[tc*8+6]; r1.w=o8[7]+b1[tc*8+7];
            *(float4*)&dst[0] = r0;
            *(float4*)&dst[4] = r1;
        }
    }
}

__global__ void k_stats2(){
    __shared__ float ss[256], ss2[256];
    int t = threadIdx.x; int c = t&63; int lane = t>>6;
    float s=0.f, s2=0.f;
    for (int r = blockIdx.x*4 + lane; r < M_PTS; r += gridDim.x*4){
        float v = g_mid[r*CO + c]; s += v; s2 += v*v;
    }
    ss[t]=s; ss2[t]=s2; __syncthreads();
    if (t < 64){
        float a = ss[t]+ss[t+64]+ss[t+128]+ss[t+192];
        float b = ss2[t]+ss2[t+64]+ss2[t+128]+ss2[t+192];
        atomicAdd(&g_sum2[c], a); atomicAdd(&g_sq2[c], b);
    }
}

__global__ void k_fin2(){
    int g = threadIdx.x;
    if (g < 32){
        float s  = g_sum2[2*g] + g_sum2[2*g+1];
        float s2 = g_sq2[2*g]  + g_sq2[2*g+1];
        float inv = 1.f/(float)(M_PTS*2);
        float mu = s*inv;
        float var = s2*inv - mu*mu;
        g_mu2[g] = mu; g_rs2[g] = rsqrtf(var + 1e-5f);
    }
}

__global__ void k_act(const float* __restrict__ gma, const float* __restrict__ bta){
    int i = blockIdx.x*256 + threadIdx.x;     // exact: M_PTS*CO multiple of 256
    int c = i & 63; int g = c >> 1;
    float v = (g_mid[i] - g_mu2[g])*g_rs2[g]*gma[c] + bta[c];
    g_act[i] = v / (1.f + expf(-v));
}

// ---------------- conv2: 27 child-level taps, 64->64, + bias + skip ----------------
__global__ __launch_bounds__(256) void k_conv2(const int* __restrict__ coords,
                                               const float* __restrict__ W2,
                                               const float* __restrict__ b2,
                                               float* __restrict__ out){
    __shared__ __align__(16) float A_s[64][68];
    __shared__ __align__(16) float W_s[64][68];
    __shared__ int   nbr_s[64][27];
    int t = threadIdx.x;
    int m0 = blockIdx.x*64;                   // M_PTS/64 = 2500 exact
    for (int e = t; e < 64*27; e += 256){
        int r = e/27, tap = e - r*27;
        int m = m0 + r, p = m>>3, o = m&7;
        int x=coords[p*4+1], y=coords[p*4+2], z=coords[p*4+3];
        int cx = 2*x + ((o>>2)&1) + tap/9 - 1;
        int cy = 2*y + ((o>>1)&1) + (tap/3)%3 - 1;
        int cz = 2*z + (o&1) + tap%3 - 1;
        int q = g_pgrid[(((cx>>1)+1)*GD + ((cy>>1)+1))*GD + ((cz>>1)+1)];
        nbr_s[r][tap] = (q >= 0) ? (q*8 + ((cx&1)<<2) + ((cy&1)<<1) + (cz&1)) : -1;
    }
    unsigned long long acc[2][4] = {};
    int tr = t>>3, tc = t&7;
    for (int tap = 0; tap < 27; tap++){
        __syncthreads();
        #pragma unroll
        for (int rep = 0; rep < 4; rep++){
            int idx = rep*256 + t;
            int r = idx>>4, kv = idx&15;
            int nb = nbr_s[r][tap];
            float4 v = make_float4(0.f,0.f,0.f,0.f);
            if (nb >= 0) v = *(const float4*)&g_act[nb*CO + kv*4];
            *(float4*)&A_s[r][kv*4] = v;
            *(float4*)&W_s[r][kv*4] = *(const float4*)&W2[(tap*CO + r)*CO + kv*4];
        }
        __syncthreads();
        #pragma unroll
        for (int kk = 0; kk < 64; kk += 4)
            conv_tile_step(A_s, W_s, kk, tr, tc, acc);
    }
    #pragma unroll
    for (int i = 0; i < 2; i++){
        int m = m0 + tr*2 + i;
        int p = m >> 3;
        float o8[8];
        #pragma unroll
        for (int q = 0; q < 4; q++) unpack2(acc[i][q], o8[2*q], o8[2*q+1]);
        const float* sk = &g_skip[p*CO + tc*8];
        float* dst = &out[m*CO + tc*8];
        float4 r0, r1;
        r0.x=o8[0]+b2[tc*8+0]+sk[0]; r0.y=o8[1]+b2[tc*8+1]+sk[1];
        r0.z=o8[2]+b2[tc*8+2]+sk[2]; r0.w=o8[3]+b2[tc*8+3]+sk[3];
        r1.x=o8[4]+b2[tc*8+4]+sk[4]; r1.y=o8[5]+b2[tc*8+5]+sk[5];
        r1.z=o8[6]+b2[tc*8+6]+sk[6]; r1.w=o8[7]+b2[tc*8+7]+sk[7];
        *(float4*)&dst[0] = r0;
        *(float4*)&dst[4] = r1;
    }
}

// ---------------- launch ----------------
extern "C" void kernel_launch(void* const* d_in, const int* in_sizes, int n_in,
                              void* d_out, int out_size){
    const float* xf    = (const float*)d_in[0];
    const int*   coords= (const int*)  d_in[1];
    const float* gn1g  = (const float*)d_in[2];
    const float* gn1b  = (const float*)d_in[3];
    const float* W1    = (const float*)d_in[4];
    const float* b1    = (const float*)d_in[5];
    const float* gn2g  = (const float*)d_in[6];
    const float* gn2b  = (const float*)d_in[7];
    const float* W2    = (const float*)d_in[8];
    const float* b2    = (const float*)d_in[9];
    const float* Ws    = (const float*)d_in[10];
    const float* bs    = (const float*)d_in[11];
    float* out = (float*)d_out;

    k_init<<<(GSZ+255)/256, 256>>>();
    k_scatter<<<(N_PTS+255)/256, 256>>>(coords);
    k_stats1<<<160, 128>>>(xf);
    k_fin1<<<1, 32>>>();
    k_h<<<N_PTS*CI/256, 256>>>(xf, gn1g, gn1b);
    k_weff<<<8*8*CI*CO/256, 256>>>(W1);
    k_skip<<<(N_PTS+63)/64, 256>>>(xf, Ws, bs);
    k_conv1<<<dim3((N_PTS+63)/64, 8), 256>>>(coords, b1);
    k_stats2<<<400, 256>>>();
    k_fin2<<<1, 32>>>();
    k_act<<<M_PTS*CO/256, 256>>>(gn2g, gn2b);
    k_conv2<<<M_PTS/64, 256>>>(coords, W2, b2, out);
}

// round 6
// speedup vs baseline: 4.4140x; 4.4140x over previous
#include <cuda_runtime.h>
#include <cuda_bf16.h>
#include <cstdint>
#include <math.h>

#define N_PTS 20000
#define M_PTS 160000
#define CI 128
#define CO 64
#define GD 34
#define GSZ (GD*GD*GD)

// ---------------- device scratch ----------------
__device__ int      g_pgrid[GSZ];
__device__ uint32_t g_h_pk[N_PTS*CI];       // silu(gn1(x)) packed bf16 hi|lo
__device__ float    g_skip[N_PTS*CO];
__device__ float    g_mid[M_PTS*CO];        // conv1 out fp32
__device__ uint32_t g_act_pk[M_PTS*CO];     // silu(gn2(mid)) packed
__device__ uint32_t g_weffT_pk[8*8*CO*CI];  // [o][n][cout][cin] packed
__device__ uint32_t g_w2t_pk[27*CO*CO];     // [tap][cout][cin] packed
__device__ float g_sum1[CI], g_sq1[CI], g_mu1[32], g_rs1[32];
__device__ float g_sum2[CO], g_sq2[CO], g_mu2[32], g_rs2[32];

// ---------------- helpers ----------------
__device__ __forceinline__ uint32_t smem_u32(const void* p){
    uint32_t a;
    asm("{ .reg .u64 t; cvta.to.shared.u64 t, %1; cvt.u32.u64 %0, t; }" : "=r"(a) : "l"(p));
    return a;
}
__device__ __forceinline__ uint32_t pack_hl(float v){
    unsigned short h = __bfloat16_as_ushort(__float2bfloat16(v));
    float hf = __bfloat162float(__ushort_as_bfloat16(h));
    unsigned short lo = __bfloat16_as_ushort(__float2bfloat16(v - hf));
    return (uint32_t)h | ((uint32_t)lo << 16);
}
__device__ __forceinline__ void ldsm4(uint32_t* r, uint32_t addr){
    asm volatile("ldmatrix.sync.aligned.m8n8.x4.shared.b16 {%0,%1,%2,%3}, [%4];"
        : "=r"(r[0]),"=r"(r[1]),"=r"(r[2]),"=r"(r[3]) : "r"(addr));
}
__device__ __forceinline__ void ldsm2(uint32_t &r0, uint32_t &r1, uint32_t addr){
    asm volatile("ldmatrix.sync.aligned.m8n8.x2.shared.b16 {%0,%1}, [%2];"
        : "=r"(r0),"=r"(r1) : "r"(addr));
}
__device__ __forceinline__ void mma16816(float* d, const uint32_t* a, uint32_t b0, uint32_t b1){
    asm volatile("mma.sync.aligned.m16n8k16.row.col.f32.bf16.bf16.f32 "
        "{%0,%1,%2,%3}, {%4,%5,%6,%7}, {%8,%9}, {%0,%1,%2,%3};"
        : "+f"(d[0]),"+f"(d[1]),"+f"(d[2]),"+f"(d[3])
        : "r"(a[0]),"r"(a[1]),"r"(a[2]),"r"(a[3]), "r"(b0),"r"(b1));
}
__device__ __forceinline__ void unpack_store(uint16_t* sH, uint16_t* sL, int vecIdx,
                                             uint4 v0, uint4 v1){
    uint4 h, lo;
    h.x  = __byte_perm(v0.x, v0.y, 0x5410); lo.x = __byte_perm(v0.x, v0.y, 0x7632);
    h.y  = __byte_perm(v0.z, v0.w, 0x5410); lo.y = __byte_perm(v0.z, v0.w, 0x7632);
    h.z  = __byte_perm(v1.x, v1.y, 0x5410); lo.z = __byte_perm(v1.x, v1.y, 0x7632);
    h.w  = __byte_perm(v1.z, v1.w, 0x5410); lo.w = __byte_perm(v1.z, v1.w, 0x7632);
    ((uint4*)sH)[vecIdx] = h;
    ((uint4*)sL)[vecIdx] = lo;
}

// ---------------- small kernels ----------------
__global__ void k_init(){
    int i = blockIdx.x*256 + threadIdx.x;
    if (i < GSZ) g_pgrid[i] = -1;
    if (i < CI){ g_sum1[i]=0.f; g_sq1[i]=0.f; }
    if (i < CO){ g_sum2[i]=0.f; g_sq2[i]=0.f; }
}
__global__ void k_scatter(const int* __restrict__ coords){
    int p = blockIdx.x*256 + threadIdx.x;
    if (p < N_PTS){
        int x=coords[p*4+1], y=coords[p*4+2], z=coords[p*4+3];
        g_pgrid[((x+1)*GD + (y+1))*GD + (z+1)] = p;
    }
}
__global__ void k_stats1(const float* __restrict__ xf){
    int c = threadIdx.x;
    float s=0.f, s2=0.f;
    for (int r = blockIdx.x; r < N_PTS; r += gridDim.x){
        float v = xf[r*CI + c]; s += v; s2 += v*v;
    }
    atomicAdd(&g_sum1[c], s); atomicAdd(&g_sq1[c], s2);
}
__global__ void k_fin1(){
    int g = threadIdx.x;
    if (g < 32){
        float s=0.f, s2=0.f;
        for (int j=0;j<4;j++){ s += g_sum1[g*4+j]; s2 += g_sq1[g*4+j]; }
        float inv = 1.f/(float)(N_PTS*4);
        float mu = s*inv, var = s2*inv - mu*mu;
        g_mu1[g] = mu; g_rs1[g] = rsqrtf(var + 1e-5f);
    }
}
__global__ void k_h(const float* __restrict__ xf,
                    const float* __restrict__ gma, const float* __restrict__ bta){
    int i = blockIdx.x*256 + threadIdx.x;
    int c = i & (CI-1); int g = c >> 2;
    float v = (xf[i] - g_mu1[g])*g_rs1[g]*gma[c] + bta[c];
    v = v / (1.f + expf(-v));
    g_h_pk[i] = pack_hl(v);
}
__global__ void k_weffT(const float* __restrict__ W1){
    int idx = blockIdx.x*256 + threadIdx.x;   // 8*8*128*64
    int cout = idx & 63, cin = (idx>>6)&127, n = (idx>>13)&7, o = idx>>16;
    int d0=(o>>2)&1, d1=(o>>1)&1, d2=o&1;
    int n0=(n>>2)&1, n1=(n>>1)&1, n2=n&1;
    float s = 0.f;
    for (int i=0;i<3;i++){
        int t0=d0+i-1; int p0=(t0>=2)?1:((t0>=0)?0:-1);
        if (p0 - d0 + 1 != n0) continue;
        for (int j=0;j<3;j++){
            int t1=d1+j-1; int p1=(t1>=2)?1:((t1>=0)?0:-1);
            if (p1 - d1 + 1 != n1) continue;
            for (int k=0;k<3;k++){
                int t2=d2+k-1; int p2=(t2>=2)?1:((t2>=0)?0:-1);
                if (p2 - d2 + 1 != n2) continue;
                s += W1[(((i*3+j)*3+k)*CI + cin)*CO + cout];
            }
        }
    }
    g_weffT_pk[((o*8+n)*CO + cout)*CI + cin] = pack_hl(s);
}
__global__ void k_w2t(const float* __restrict__ W2){
    int idx = blockIdx.x*256 + threadIdx.x;   // 27*64*64
    if (idx >= 27*CO*CO) return;
    int cout = idx & 63, cin = (idx>>6)&63, tap = idx>>12;
    g_w2t_pk[(tap*CO + cout)*CO + cin] = pack_hl(W2[(tap*CO + cin)*CO + cout]);
}

// ---------------- skip GEMM (scalar fp32, tiny) ----------------
__device__ __forceinline__ void mma_row(float4 a, float4 w0, float4 w1, float4 w2, float4 w3,
                                        float acc[4]){
    acc[0]=fmaf(a.x,w0.x,acc[0]); acc[0]=fmaf(a.y,w1.x,acc[0]); acc[0]=fmaf(a.z,w2.x,acc[0]); acc[0]=fmaf(a.w,w3.x,acc[0]);
    acc[1]=fmaf(a.x,w0.y,acc[1]); acc[1]=fmaf(a.y,w1.y,acc[1]); acc[1]=fmaf(a.z,w2.y,acc[1]); acc[1]=fmaf(a.w,w3.y,acc[1]);
    acc[2]=fmaf(a.x,w0.z,acc[2]); acc[2]=fmaf(a.y,w1.z,acc[2]); acc[2]=fmaf(a.z,w2.z,acc[2]); acc[2]=fmaf(a.w,w3.z,acc[2]);
    acc[3]=fmaf(a.x,w0.w,acc[3]); acc[3]=fmaf(a.y,w1.w,acc[3]); acc[3]=fmaf(a.z,w2.w,acc[3]); acc[3]=fmaf(a.w,w3.w,acc[3]);
}
__global__ __launch_bounds__(256) void k_skip(const float* __restrict__ xf,
                                              const float* __restrict__ Ws,
                                              const float* __restrict__ bs){
    __shared__ __align__(16) float A_s[64][68];
    __shared__ __align__(16) float W_s[64][68];
    int t = threadIdx.x;
    int p0 = blockIdx.x*64;
    float acc[4][4] = {};
    int tr = t>>4, tc = t&15;
    for (int ck = 0; ck < 2; ck++){
        __syncthreads();
        #pragma unroll
        for (int rep = 0; rep < 4; rep++){
            int idx = rep*256 + t;
            int r = idx>>4, kv = idx&15;
            int p = p0 + r;
            float4 v = make_float4(0.f,0.f,0.f,0.f);
            if (p < N_PTS) v = *(const float4*)&xf[p*CI + ck*64 + kv*4];
            *(float4*)&A_s[r][kv*4] = v;
            *(float4*)&W_s[r][kv*4] = *(const float4*)&Ws[(ck*64 + r)*CO + kv*4];
        }
        __syncthreads();
        #pragma unroll
        for (int kk = 0; kk < 64; kk += 4){
            float4 w0 = *(float4*)&W_s[kk+0][tc*4];
            float4 w1 = *(float4*)&W_s[kk+1][tc*4];
            float4 w2 = *(float4*)&W_s[kk+2][tc*4];
            float4 w3 = *(float4*)&W_s[kk+3][tc*4];
            #pragma unroll
            for (int i = 0; i < 4; i++){
                float4 a = *(float4*)&A_s[tr*4+i][kk];
                mma_row(a, w0, w1, w2, w3, acc[i]);
            }
        }
    }
    #pragma unroll
    for (int i = 0; i < 4; i++){
        int p = p0 + tr*4 + i;
        if (p < N_PTS){
            float4 r;
            r.x = acc[i][0] + bs[tc*4+0];
            r.y = acc[i][1] + bs[tc*4+1];
            r.z = acc[i][2] + bs[tc*4+2];
            r.w = acc[i][3] + bs[tc*4+3];
            *(float4*)&g_skip[p*CO + tc*4] = r;
        }
    }
}

// ---------------- shared MMA chunk: A[128][32] x B^T[64][32], acc 16x64/warp ----------------
__device__ __forceinline__ void mma_chunk(uint32_t bAh, uint32_t bAl, uint32_t bBh, uint32_t bBl,
                                          int l, int w, float acc[8][4]){
    uint32_t ah[2][4], al[2][4];
    #pragma unroll
    for (int ks = 0; ks < 2; ks++){
        int tile = l>>3, i = l&7;
        int row = w*16 + (tile&1)*8 + i;
        int col = ks*16 + (tile>>1)*8;
        ldsm4(ah[ks], bAh + row*80 + col*2);
        ldsm4(al[ks], bAl + row*80 + col*2);
    }
    int li = l & 15;
    #pragma unroll
    for (int j = 0; j < 8; j++){
        #pragma unroll
        for (int ks = 0; ks < 2; ks++){
            int row = j*8 + (li&7);
            int col = ks*16 + (li>>3)*8;
            uint32_t bh0,bh1,bl0,bl1;
            ldsm2(bh0,bh1, bBh + row*80 + col*2);
            ldsm2(bl0,bl1, bBl + row*80 + col*2);
            mma16816(acc[j], ah[ks], bh0, bh1);
            mma16816(acc[j], ah[ks], bl0, bl1);
            mma16816(acc[j], al[ks], bh0, bh1);
        }
    }
}

// ---------------- conv1: 8 folded parent-neighbors, K=128 in 4 chunks of 32 ----------------
__global__ __launch_bounds__(256) void k_conv1_mma(const int* __restrict__ coords,
                                                   const float* __restrict__ b1){
    __shared__ __align__(16) uint16_t sAh[128*40], sAl[128*40];
    __shared__ __align__(16) uint16_t sBh[64*40],  sBl[64*40];
    __shared__ int s_nbr[8][128];
    int t = threadIdx.x, l = t&31, w = t>>5;
    int p0 = blockIdx.x*128;
    int o  = blockIdx.y;
    int dx=(o>>2)&1, dy=(o>>1)&1, dz=o&1;

    if (t < 128){
        int p = p0 + t;
        if (p < N_PTS){
            int x=coords[p*4+1], y=coords[p*4+2], z=coords[p*4+3];
            #pragma unroll
            for (int n = 0; n < 8; n++){
                int ox = dx-1+((n>>2)&1), oy = dy-1+((n>>1)&1), oz = dz-1+(n&1);
                s_nbr[n][t] = g_pgrid[((x+ox+1)*GD + (y+oy+1))*GD + (z+oz+1)];
            }
        } else {
            #pragma unroll
            for (int n = 0; n < 8; n++) s_nbr[n][t] = -1;
        }
    }
    uint32_t bAh = smem_u32(sAh), bAl = smem_u32(sAl);
    uint32_t bBh = smem_u32(sBh), bBl = smem_u32(sBl);
    float acc[8][4] = {};

    for (int st = 0; st < 32; st++){
        int n = st>>2, q = st&3;
        __syncthreads();
        #pragma unroll
        for (int it = 0; it < 2; it++){
            int idx = it*256 + t, r = idx>>2, oct = idx&3;
            int nb = s_nbr[n][r];
            uint4 v0 = make_uint4(0,0,0,0), v1 = v0;
            if (nb >= 0){
                const uint4* src = (const uint4*)&g_h_pk[nb*CI + q*32 + oct*8];
                v0 = src[0]; v1 = src[1];
            }
            unpack_store(sAh, sAl, r*5 + oct, v0, v1);
        }
        {
            int r = t>>2, oct = t&3;
            const uint4* src = (const uint4*)&g_weffT_pk[((o*8+n)*CO + r)*CI + q*32 + oct*8];
            unpack_store(sBh, sBl, r*5 + oct, src[0], src[1]);
        }
        __syncthreads();
        mma_chunk(bAh, bAl, bBh, bBl, l, w, acc);
    }
    int r0 = w*16 + (l>>2);
    #pragma unroll
    for (int j = 0; j < 8; j++){
        int col = j*8 + (l&3)*2;
        int p_0 = p0 + r0;
        if (p_0 < N_PTS){
            float2 v; v.x = acc[j][0] + b1[col]; v.y = acc[j][1] + b1[col+1];
            *(float2*)&g_mid[((size_t)p_0*8 + o)*CO + col] = v;
        }
        int p_1 = p0 + r0 + 8;
        if (p_1 < N_PTS){
            float2 v; v.x = acc[j][2] + b1[col]; v.y = acc[j][3] + b1[col+1];
            *(float2*)&g_mid[((size_t)p_1*8 + o)*CO + col] = v;
        }
    }
}

__global__ void k_stats2(){
    __shared__ float ss[256], ss2[256];
    int t = threadIdx.x; int c = t&63; int lane = t>>6;
    float s=0.f, s2=0.f;
    for (int r = blockIdx.x*4 + lane; r < M_PTS; r += gridDim.x*4){
        float v = g_mid[r*CO + c]; s += v; s2 += v*v;
    }
    ss[t]=s; ss2[t]=s2; __syncthreads();
    if (t < 64){
        float a = ss[t]+ss[t+64]+ss[t+128]+ss[t+192];
        float b = ss2[t]+ss2[t+64]+ss2[t+128]+ss2[t+192];
        atomicAdd(&g_sum2[c], a); atomicAdd(&g_sq2[c], b);
    }
}
__global__ void k_fin2(){
    int g = threadIdx.x;
    if (g < 32){
        float s  = g_sum2[2*g] + g_sum2[2*g+1];
        float s2 = g_sq2[2*g]  + g_sq2[2*g+1];
        float inv = 1.f/(float)(M_PTS*2);
        float mu = s*inv, var = s2*inv - mu*mu;
        g_mu2[g] = mu; g_rs2[g] = rsqrtf(var + 1e-5f);
    }
}
__global__ void k_act(const float* __restrict__ gma, const float* __restrict__ bta){
    int i = blockIdx.x*256 + threadIdx.x;
    int c = i & 63; int g = c >> 1;
    float v = (g_mid[i] - g_mu2[g])*g_rs2[g]*gma[c] + bta[c];
    v = v / (1.f + expf(-v));
    g_act_pk[i] = pack_hl(v);
}

// ---------------- conv2: 27 taps, K=64 in 2 chunks of 32, + bias + skip ----------------
__global__ __launch_bounds__(256) void k_conv2_mma(const int* __restrict__ coords,
                                                   const float* __restrict__ b2,
                                                   float* __restrict__ out){
    __shared__ __align__(16) uint16_t sAh[128*40], sAl[128*40];
    __shared__ __align__(16) uint16_t sBh[64*40],  sBl[64*40];
    __shared__ int s_nbr[27][128];
    int t = threadIdx.x, l = t&31, w = t>>5;
    int m0 = blockIdx.x*128;                  // M_PTS/128 = 1250 exact

    if (t < 128){
        int m = m0 + t, p = m>>3, oo = m&7;
        int cx = 2*coords[p*4+1] + ((oo>>2)&1);
        int cy = 2*coords[p*4+2] + ((oo>>1)&1);
        int cz = 2*coords[p*4+3] + (oo&1);
        #pragma unroll
        for (int tap = 0; tap < 27; tap++){
            int ax = cx + tap/9 - 1;
            int ay = cy + (tap/3)%3 - 1;
            int az = cz + tap%3 - 1;
            int q = g_pgrid[(((ax>>1)+1)*GD + ((ay>>1)+1))*GD + ((az>>1)+1)];
            s_nbr[tap][t] = (q >= 0) ? (q*8 + ((ax&1)<<2) + ((ay&1)<<1) + (az&1)) : -1;
        }
    }
    uint32_t bAh = smem_u32(sAh), bAl = smem_u32(sAl);
    uint32_t bBh = smem_u32(sBh), bBl = smem_u32(sBl);
    float acc[8][4] = {};

    for (int tap = 0; tap < 27; tap++){
        for (int ck = 0; ck < 2; ck++){
            __syncthreads();
            #pragma unroll
            for (int it = 0; it < 2; it++){
                int idx = it*256 + t, r = idx>>2, oct = idx&3;
                int nb = s_nbr[tap][r];
                uint4 v0 = make_uint4(0,0,0,0), v1 = v0;
                if (nb >= 0){
                    const uint4* src = (const uint4*)&g_act_pk[nb*CO + ck*32 + oct*8];
                    v0 = src[0]; v1 = src[1];
                }
                unpack_store(sAh, sAl, r*5 + oct, v0, v1);
            }
            {
                int r = t>>2, oct = t&3;
                const uint4* src = (const uint4*)&g_w2t_pk[(tap*CO + r)*CO + ck*32 + oct*8];
                unpack_store(sBh, sBl, r*5 + oct, src[0], src[1]);
            }
            __syncthreads();
            mma_chunk(bAh, bAl, bBh, bBl, l, w, acc);
        }
    }
    int r0 = w*16 + (l>>2);
    #pragma unroll
    for (int j = 0; j < 8; j++){
        int col = j*8 + (l&3)*2;
        {
            int m = m0 + r0, p = m>>3;
            float2 v;
            v.x = acc[j][0] + b2[col]   + g_skip[p*CO + col];
            v.y = acc[j][1] + b2[col+1] + g_skip[p*CO + col+1];
            *(float2*)&out[(size_t)m*CO + col] = v;
        }
        {
            int m = m0 + r0 + 8, p = m>>3;
            float2 v;
            v.x = acc[j][2] + b2[col]   + g_skip[p*CO + col];
            v.y = acc[j][3] + b2[col+1] + g_skip[p*CO + col+1];
            *(float2*)&out[(size_t)m*CO + col] = v;
        }
    }
}

// ---------------- launch ----------------
extern "C" void kernel_launch(void* const* d_in, const int* in_sizes, int n_in,
                              void* d_out, int out_size){
    const float* xf    = (const float*)d_in[0];
    const int*   coords= (const int*)  d_in[1];
    const float* gn1g  = (const float*)d_in[2];
    const float* gn1b  = (const float*)d_in[3];
    const float* W1    = (const float*)d_in[4];
    const float* b1    = (const float*)d_in[5];
    const float* gn2g  = (const float*)d_in[6];
    const float* gn2b  = (const float*)d_in[7];
    const float* W2    = (const float*)d_in[8];
    const float* b2    = (const float*)d_in[9];
    const float* Ws    = (const float*)d_in[10];
    const float* bs    = (const float*)d_in[11];
    float* out = (float*)d_out;

    k_init<<<(GSZ+255)/256, 256>>>();
    k_scatter<<<(N_PTS+255)/256, 256>>>(coords);
    k_stats1<<<160, 128>>>(xf);
    k_fin1<<<1, 32>>>();
    k_h<<<N_PTS*CI/256, 256>>>(xf, gn1g, gn1b);
    k_weffT<<<8*8*CI*CO/256, 256>>>(W1);
    k_w2t<<<(27*CO*CO+255)/256, 256>>>(W2);
    k_skip<<<(N_PTS+63)/64, 256>>>(xf, Ws, bs);
    k_conv1_mma<<<dim3((N_PTS+127)/128, 8), 256>>>(coords, b1);
    k_stats2<<<400, 256>>>();
    k_fin2<<<1, 32>>>();
    k_act<<<M_PTS*CO/256, 256>>>(gn2g, gn2b);
    k_conv2_mma<<<M_PTS/128, 256>>>(coords, b2, out);
}